// round 13
// baseline (speedup 1.0000x reference)
#include <cuda_runtime.h>
#include <cuda_fp16.h>
#include <math.h>
#include <stdint.h>

#define N_BATCH 4
#define C_DIM   512
#define L_DIM   4096
#define NGROUP  32
#define CPG     16
#define GN_EPS  1e-5f
#define CL      ((size_t)C_DIM * L_DIM)
#define LL      ((size_t)L_DIM * L_DIM)

typedef __half f16;

// ---------------- scratch ----------------
__device__ f16   g_ht[N_BATCH * CL];
__device__ f16   g_q [N_BATCH * CL];       // [L, C], pre-scaled by att_scale
__device__ f16   g_k [N_BATCH * CL];       // [L, C]
__device__ f16   g_v [N_BATCH * CL];       // [C, L]
__device__ f16   g_o [N_BATCH * CL];       // [L, C]
__device__ f16   g_p [N_BATCH * LL];       // unnormalized exp(scores)
__device__ float g_psum[N_BATCH * L_DIM * 16];
__device__ f16   g_wq[C_DIM * C_DIM];
__device__ f16   g_wk[C_DIM * C_DIM];
__device__ f16   g_wv[C_DIM * C_DIM];
__device__ f16   g_wo[C_DIM * C_DIM];

__global__ void cvt_w_kernel(const float* __restrict__ wq, const float* __restrict__ wk,
                             const float* __restrict__ wv, const float* __restrict__ wo)
{
    int i = blockIdx.x * 256 + threadIdx.x;
    g_wq[i] = __float2half(wq[i]);
    g_wk[i] = __float2half(wk[i]);
    g_wv[i] = __float2half(wv[i]);
    g_wo[i] = __float2half(wo[i]);
}

// ---------------- GroupNorm -> h_t[L, C] f16 ----------------
__global__ __launch_bounds__(512) void gn_kernel(const float* __restrict__ x,
                                                 const float* __restrict__ scale,
                                                 const float* __restrict__ bias,
                                                 f16* __restrict__ ht)
{
    const int n = blockIdx.x >> 5;
    const int g = blockIdx.x & 31;
    const float* __restrict__ xg = x + ((size_t)n * C_DIM + (size_t)g * CPG) * L_DIM;
    f16* __restrict__ hb = ht + (size_t)n * CL + g * CPG;
    const int tid = threadIdx.x;

    const float4* xv = (const float4*)xg;
    float s = 0.f, ss = 0.f;
    for (int i = tid; i < CPG * L_DIM / 4; i += 512) {
        float4 v = xv[i];
        s  += v.x + v.y + v.z + v.w;
        ss += v.x*v.x + v.y*v.y + v.z*v.z + v.w*v.w;
    }
    __shared__ float rs[512], rss[512];
    rs[tid] = s; rss[tid] = ss;
    __syncthreads();
    for (int st = 256; st > 0; st >>= 1) {
        if (tid < st) { rs[tid] += rs[tid+st]; rss[tid] += rss[tid+st]; }
        __syncthreads();
    }
    const float inv_n = 1.f / (float)(CPG * L_DIM);
    const float mean = rs[0] * inv_n;
    const float var  = rss[0] * inv_n - mean * mean;
    const float rstd = rsqrtf(var + GN_EPS);

    __shared__ float tile[16][260];
    for (int l0 = 0; l0 < L_DIM; l0 += 256) {
        #pragma unroll
        for (int j = 0; j < 2; j++) {
            int vi = tid + j * 512;
            int c  = vi >> 6;
            int lv = vi & 63;
            float4 v = xv[c * (L_DIM/4) + (l0 >> 2) + lv];
            float sc = scale[g*CPG + c] * rstd;
            float bi = bias[g*CPG + c] - mean * sc;
            tile[c][4*lv+0] = v.x*sc + bi;
            tile[c][4*lv+1] = v.y*sc + bi;
            tile[c][4*lv+2] = v.z*sc + bi;
            tile[c][4*lv+3] = v.w*sc + bi;
        }
        __syncthreads();
        #pragma unroll
        for (int j = 0; j < 2; j++) {
            int vi = tid + j * 512;
            int l  = vi >> 2;
            int c4 = vi & 3;
            __half2 p0 = __floats2half2_rn(tile[4*c4+0][l], tile[4*c4+1][l]);
            __half2 p1 = __floats2half2_rn(tile[4*c4+2][l], tile[4*c4+3][l]);
            f16* dst = hb + (size_t)(l0 + l) * C_DIM + 4*c4;
            *(__half2*)(dst)     = p0;
            *(__half2*)(dst + 2) = p1;
        }
        __syncthreads();
    }
}

// ---------------- MMA helpers ----------------
__device__ __forceinline__ void mma_f16(uint32_t* d, const uint32_t* a, const uint32_t* b) {
    asm volatile(
        "mma.sync.aligned.m16n8k16.row.col.f16.f16.f16.f16 "
        "{%0,%1},{%2,%3,%4,%5},{%6,%7},{%0,%1};"
        : "+r"(d[0]), "+r"(d[1])
        : "r"(a[0]), "r"(a[1]), "r"(a[2]), "r"(a[3]), "r"(b[0]), "r"(b[1]));
}

__device__ __forceinline__ void ldsm_x4(uint32_t* r, uint32_t addr) {
    asm volatile("ldmatrix.sync.aligned.m8n8.x4.shared.b16 {%0,%1,%2,%3}, [%4];"
        : "=r"(r[0]), "=r"(r[1]), "=r"(r[2]), "=r"(r[3]) : "r"(addr));
}

#define CP16(dst, src) asm volatile("cp.async.cg.shared.global [%0], [%1], 16;" :: "r"(dst), "l"(src))
#define CP_COMMIT()    asm volatile("cp.async.commit_group;")
#define CP_WAIT(n)     asm volatile("cp.async.wait_group %0;" :: "n"(n))

// ---- 128-thread config (qkv, av, final): CTA 128x128, warp 64x64, BK=32 ----
#define BM 128
#define BN 128
#define PITCH 40
#define TILEO (128 * PITCH)
#define STAGEE (2 * TILEO)
#define SMEM_BYTES (2 * STAGEE * 2)     // 40960 B -> 4 CTAs/SM
#define FSMEM_BYTES (128 * 132 * 4)     // 67584 B (final kernel fp32 staging)

#define GEMM_MAINLOOP(A, B, K)                                                      \
    const uint32_t smem_u = (uint32_t)__cvta_generic_to_shared(sm);                 \
    const uint32_t a_off = ((wm + (lane & 15)) * PITCH + ((lane >> 4) << 3)) * 2;   \
    const uint32_t b_off = ((wn + (lane & 7) + ((lane >> 4) << 3)) * PITCH          \
                            + (((lane >> 3) & 1) << 3)) * 2;                        \
    uint32_t acc[4][8][2];                                                          \
    _Pragma("unroll") for (int i = 0; i < 4; i++)                                   \
        _Pragma("unroll") for (int j = 0; j < 8; j++)                               \
            { acc[i][j][0] = 0u; acc[i][j][1] = 0u; }                               \
    auto load_tiles = [&](int k0, int s) {                                          \
        f16* As = sm + s * STAGEE;                                                  \
        f16* Bs = As + TILEO;                                                       \
        _Pragma("unroll") for (int i = 0; i < 4; i++) {                             \
            int id  = tid + i * 128;                                                \
            int row = id >> 2;                                                      \
            int cof = (id & 3) << 3;                                                \
            CP16((uint32_t)__cvta_generic_to_shared(As + row * PITCH + cof),        \
                 (A) + (size_t)(bm + row) * (K) + k0 + cof);                        \
            CP16((uint32_t)__cvta_generic_to_shared(Bs + row * PITCH + cof),        \
                 (B) + (size_t)(bn + row) * (K) + k0 + cof);                        \
        }                                                                           \
    };                                                                              \
    load_tiles(0, 0);                                                               \
    CP_COMMIT();                                                                    \
    int s = 0;                                                                      \
    _Pragma("unroll 1") for (int it = 0; it < (K) / 32; it++) {                     \
        CP_WAIT(0);                                                                 \
        __syncthreads();                                                            \
        if (it + 1 < (K) / 32) { load_tiles((it + 1) << 5, s ^ 1); CP_COMMIT(); }   \
        const uint32_t As_u = smem_u + s * (STAGEE * 2);                            \
        const uint32_t Bs_u = As_u + TILEO * 2;                                     \
        _Pragma("unroll") for (int ks = 0; ks < 2; ks++) {                          \
            const uint32_t kadd = ks * 32;                                          \
            uint32_t a[4][4], b[8][2];                                              \
            _Pragma("unroll") for (int mt = 0; mt < 4; mt++)                        \
                ldsm_x4(a[mt], As_u + a_off + mt * (16 * PITCH * 2) + kadd);        \
            _Pragma("unroll") for (int p = 0; p < 4; p++) {                         \
                uint32_t r[4];                                                      \
                ldsm_x4(r, Bs_u + b_off + p * (16 * PITCH * 2) + kadd);             \
                b[2*p][0]   = r[0]; b[2*p][1]   = r[1];                             \
                b[2*p+1][0] = r[2]; b[2*p+1][1] = r[3];                             \
            }                                                                       \
            _Pragma("unroll") for (int mt = 0; mt < 4; mt++)                        \
                _Pragma("unroll") for (int nt = 0; nt < 8; nt++)                    \
                    mma_f16(acc[mt][nt], a[mt], b[nt]);                             \
        }                                                                           \
        s ^= 1;                                                                     \
    }

// ================= fused QKV projection =================
__global__ __launch_bounds__(128, 4)
void qkv_kernel(const f16* __restrict__ ht, float att_scale,
                const float* __restrict__ bq, const float* __restrict__ bk,
                const float* __restrict__ bv)
{
    extern __shared__ f16 sm[];
    const int which = blockIdx.z >> 2;
    const int nb    = blockIdx.z & 3;
    const f16* A = ht + (size_t)nb * CL;
    const f16* B = (which == 0) ? g_wq : (which == 1) ? g_wk : g_wv;
    const float* bias = (which == 0) ? bq : (which == 1) ? bk : bv;

    const int tid = threadIdx.x;
    const int bm = blockIdx.y * BM;
    const int bn = blockIdx.x * BN;
    const int lane = tid & 31;
    const int warp = tid >> 5;
    const int wm   = (warp >> 1) << 6;
    const int wn   = (warp & 1) << 6;
    const int gid  = lane >> 2;
    const int tig  = lane & 3;

    GEMM_MAINLOOP(A, B, C_DIM)

    if (which <= 1) {
        const float scl = (which == 0) ? att_scale : 1.f;
        f16* C = ((which == 0) ? g_q : g_k) + (size_t)nb * CL;
        #pragma unroll
        for (int mt = 0; mt < 4; mt++) {
            #pragma unroll
            for (int nt = 0; nt < 8; nt++) {
                int m0 = bm + wm + mt * 16 + gid;
                int n0 = bn + wn + nt * 8 + 2 * tig;
                float b0 = bias[n0], b1 = bias[n0 + 1];
                __half2 v0 = *(__half2*)&acc[mt][nt][0];
                __half2 v1 = *(__half2*)&acc[mt][nt][1];
                float d0 = (__low2float(v0)  + b0) * scl;
                float d1 = (__high2float(v0) + b1) * scl;
                float d2 = (__low2float(v1)  + b0) * scl;
                float d3 = (__high2float(v1) + b1) * scl;
                *(__half2*)&C[(size_t)m0 * C_DIM + n0]       = __floats2half2_rn(d0, d1);
                *(__half2*)&C[(size_t)(m0 + 8) * C_DIM + n0] = __floats2half2_rn(d2, d3);
            }
        }
    } else {
        f16* smh = sm;
        __syncthreads();
        #pragma unroll
        for (int mt = 0; mt < 4; mt++) {
            #pragma unroll
            for (int nt = 0; nt < 8; nt++) {
                int ml = wm + mt * 16 + gid;
                int nl = wn + nt * 8 + 2 * tig;
                int n0 = bn + nl;
                float b0 = bias[n0], b1 = bias[n0 + 1];
                __half2 v0 = *(__half2*)&acc[mt][nt][0];
                __half2 v1 = *(__half2*)&acc[mt][nt][1];
                smh[nl * 136 + ml]           = __float2half(__low2float(v0)  + b0);
                smh[(nl + 1) * 136 + ml]     = __float2half(__high2float(v0) + b1);
                smh[nl * 136 + ml + 8]       = __float2half(__low2float(v1)  + b0);
                smh[(nl + 1) * 136 + ml + 8] = __float2half(__high2float(v1) + b1);
            }
        }
        __syncthreads();
        f16* C = g_v + (size_t)nb * CL;
        #pragma unroll
        for (int i = 0; i < 16; i++) {
            int idx = tid + i * 128;
            int row = idx >> 4;
            int m = (idx & 15) << 3;
            uint4 v = *(uint4*)&smh[row * 136 + m];
            *(uint4*)&C[(size_t)(bn + row) * L_DIM + bm + m] = v;
        }
    }
}

// ================= scores: CTA 128x256, 256 threads, staged stores =================
#define SBM 128
#define SBN 256
#define STILEA (128 * PITCH)
#define STILEB (256 * PITCH)
#define SSTAGE (STILEA + STILEB)
#define SC_SMEM (2 * SSTAGE * 2)        // 61440 B -> 2 CTAs/SM

__global__ __launch_bounds__(256, 2)
void scores_kernel()
{
    extern __shared__ f16 sm[];
    const int nb = blockIdx.z;
    const f16* A = g_q + (size_t)nb * CL;
    const f16* B = g_k + (size_t)nb * CL;
    f16* C = g_p + (size_t)nb * LL;

    const int tid = threadIdx.x;
    const int bm = blockIdx.y * SBM;
    const int bn = blockIdx.x * SBN;
    const int lane = tid & 31;
    const int warp = tid >> 5;
    const int wm   = (warp >> 2) << 6;   // 0 / 64
    const int wn   = (warp & 3) << 6;    // 0..192
    const int gid  = lane >> 2;
    const int tig  = lane & 3;

    const uint32_t smem_u = (uint32_t)__cvta_generic_to_shared(sm);
    const uint32_t a_off = ((wm + (lane & 15)) * PITCH + ((lane >> 4) << 3)) * 2;
    const uint32_t b_off = ((wn + (lane & 7) + ((lane >> 4) << 3)) * PITCH
                            + (((lane >> 3) & 1) << 3)) * 2;

    uint32_t acc[4][8][2];
    #pragma unroll
    for (int i = 0; i < 4; i++)
        #pragma unroll
        for (int j = 0; j < 8; j++) { acc[i][j][0] = 0u; acc[i][j][1] = 0u; }

    auto load_tiles = [&](int k0, int s) {
        f16* As = sm + s * SSTAGE;
        f16* Bs = As + STILEA;
        #pragma unroll
        for (int i = 0; i < 2; i++) {
            int id  = tid + i * 256;
            int row = id >> 2;
            int cof = (id & 3) << 3;
            CP16((uint32_t)__cvta_generic_to_shared(As + row * PITCH + cof),
                 A + (size_t)(bm + row) * C_DIM + k0 + cof);
        }
        #pragma unroll
        for (int i = 0; i < 4; i++) {
            int id  = tid + i * 256;
            int row = id >> 2;
            int cof = (id & 3) << 3;
            CP16((uint32_t)__cvta_generic_to_shared(Bs + row * PITCH + cof),
                 B + (size_t)(bn + row) * C_DIM + k0 + cof);
        }
    };

    load_tiles(0, 0);
    CP_COMMIT();
    int s = 0;
    #pragma unroll 1
    for (int it = 0; it < C_DIM / 32; it++) {
        CP_WAIT(0);
        __syncthreads();
        if (it + 1 < C_DIM / 32) { load_tiles((it + 1) << 5, s ^ 1); CP_COMMIT(); }
        const uint32_t As_u = smem_u + s * (SSTAGE * 2);
        const uint32_t Bs_u = As_u + STILEA * 2;
        #pragma unroll
        for (int ks = 0; ks < 2; ks++) {
            const uint32_t kadd = ks * 32;
            uint32_t a[4][4], b[8][2];
            #pragma unroll
            for (int mt = 0; mt < 4; mt++)
                ldsm_x4(a[mt], As_u + a_off + mt * (16 * PITCH * 2) + kadd);
            #pragma unroll
            for (int p = 0; p < 4; p++) {
                uint32_t r[4];
                ldsm_x4(r, Bs_u + b_off + p * (16 * PITCH * 2) + kadd);
                b[2*p][0]   = r[0]; b[2*p][1]   = r[1];
                b[2*p+1][0] = r[2]; b[2*p+1][1] = r[3];
            }
            #pragma unroll
            for (int mt = 0; mt < 4; mt++)
                #pragma unroll
                for (int nt = 0; nt < 8; nt++)
                    mma_f16(acc[mt][nt], a[mt], b[nt]);
        }
        s ^= 1;
    }

    // ---- epilogue: exp (repack to f16), partial row sums ----
    float rowA[4], rowB[4];
    #pragma unroll
    for (int mt = 0; mt < 4; mt++) { rowA[mt] = 0.f; rowB[mt] = 0.f; }
    #pragma unroll
    for (int mt = 0; mt < 4; mt++) {
        #pragma unroll
        for (int nt = 0; nt < 8; nt++) {
            __half2 v0 = *(__half2*)&acc[mt][nt][0];
            __half2 v1 = *(__half2*)&acc[mt][nt][1];
            float e0 = __expf(__low2float(v0));
            float e1 = __expf(__high2float(v0));
            float e2 = __expf(__low2float(v1));
            float e3 = __expf(__high2float(v1));
            rowA[mt] += e0 + e1;
            rowB[mt] += e2 + e3;
            __half2 h0 = __floats2half2_rn(e0, e1);
            __half2 h1 = __floats2half2_rn(e2, e3);
            acc[mt][nt][0] = *(uint32_t*)&h0;
            acc[mt][nt][1] = *(uint32_t*)&h1;
        }
    }
    float* part = (float*)sm;           // [4][128]
    __syncthreads();                    // mainloop smem reads done
    #pragma unroll
    for (int mt = 0; mt < 4; mt++) {
        float sA = rowA[mt], sB = rowB[mt];
        sA += __shfl_xor_sync(0xffffffffu, sA, 1);
        sA += __shfl_xor_sync(0xffffffffu, sA, 2);
        sB += __shfl_xor_sync(0xffffffffu, sB, 1);
        sB += __shfl_xor_sync(0xffffffffu, sB, 2);
        if (tig == 0) {
            part[(warp & 3) * 128 + wm + mt * 16 + gid]     = sA;
            part[(warp & 3) * 128 + wm + mt * 16 + gid + 8] = sB;
        }
    }
    __syncthreads();
    if (tid < 128) {
        float sv = part[tid] + part[128 + tid] + part[256 + tid] + part[384 + tid];
        g_psum[((size_t)nb * L_DIM + bm + tid) * 16 + blockIdx.x] = sv;
    }

    // ---- staged coalesced stores: two passes of 128 cols ----
    f16* smh = sm;                      // [128][136]
    #pragma unroll
    for (int p = 0; p < 2; p++) {
        __syncthreads();
        if (((warp & 3) >> 1) == p) {
            const int nbase = wn & 127;  // 0 or 64 within this pass (FIX: was & 63)
            #pragma unroll
            for (int mt = 0; mt < 4; mt++) {
                #pragma unroll
                for (int nt = 0; nt < 8; nt++) {
                    int ml = wm + mt * 16 + gid;
                    int nl = nbase + nt * 8 + 2 * tig;
                    *(__half2*)&smh[ml * 136 + nl]       = *(__half2*)&acc[mt][nt][0];
                    *(__half2*)&smh[(ml + 8) * 136 + nl] = *(__half2*)&acc[mt][nt][1];
                }
            }
        }
        __syncthreads();
        #pragma unroll
        for (int i = 0; i < 8; i++) {
            int idx = tid + i * 256;
            int row = idx >> 4;
            int m = (idx & 15) << 3;
            uint4 v = *(uint4*)&smh[row * 136 + m];
            *(uint4*)&C[(size_t)(bm + row) * L_DIM + bn + p * 128 + m] = v;
        }
    }
}

// ================= AV: O = (P V^T) / rowsum (psum reduced in-kernel) =================
__global__ __launch_bounds__(128, 4)
void av_kernel()
{
    extern __shared__ f16 sm[];
    __shared__ float sinv[128];
    const int nb = blockIdx.z;
    const f16* A = g_p + (size_t)nb * LL;
    const f16* B = g_v + (size_t)nb * CL;
    f16* C = g_o + (size_t)nb * CL;

    const int tid = threadIdx.x;
    const int bm = blockIdx.y * BM;
    const int bn = blockIdx.x * BN;
    const int lane = tid & 31;
    const int warp = tid >> 5;
    const int wm   = (warp >> 1) << 6;
    const int wn   = (warp & 1) << 6;
    const int gid  = lane >> 2;
    const int tig  = lane & 3;

    {
        const float* pp = g_psum + ((size_t)nb * L_DIM + bm + tid) * 16;
        float sv = 0.f;
        #pragma unroll
        for (int i = 0; i < 16; i++) sv += pp[i];
        sinv[tid] = 1.f / sv;
    }

    GEMM_MAINLOOP(A, B, L_DIM)

    #pragma unroll
    for (int mt = 0; mt < 4; mt++) {
        int ml = wm + mt * 16 + gid;
        int m0 = bm + ml;
        float i0 = sinv[ml], i1 = sinv[ml + 8];
        #pragma unroll
        for (int nt = 0; nt < 8; nt++) {
            int n0 = bn + wn + nt * 8 + 2 * tig;
            __half2 v0 = *(__half2*)&acc[mt][nt][0];
            __half2 v1 = *(__half2*)&acc[mt][nt][1];
            *(__half2*)&C[(size_t)m0 * C_DIM + n0] =
                __floats2half2_rn(__low2float(v0) * i0, __high2float(v0) * i0);
            *(__half2*)&C[(size_t)(m0 + 8) * C_DIM + n0] =
                __floats2half2_rn(__low2float(v1) * i1, __high2float(v1) * i1);
        }
    }
}

// ================= final projection: out = (O x wo^T)^T + bo + x =================
__global__ __launch_bounds__(128, 3)
void final_kernel(float* __restrict__ Cg, const float* __restrict__ bias,
                  const float* __restrict__ resg)
{
    extern __shared__ f16 sm[];
    const int tid = threadIdx.x;
    const int bm = blockIdx.y * BM;
    const int bn = blockIdx.x * BN;
    const f16* A = g_o + (size_t)blockIdx.z * CL;
    const f16* B = g_wo;
    const float* R = resg + (size_t)blockIdx.z * CL;
    float* C = Cg + (size_t)blockIdx.z * CL;

    const int lane = tid & 31;
    const int warp = tid >> 5;
    const int wm   = (warp >> 1) << 6;
    const int wn   = (warp & 1) << 6;
    const int gid  = lane >> 2;
    const int tig  = lane & 3;

    GEMM_MAINLOOP(A, B, C_DIM)

    float* smf = (float*)sm;
    __syncthreads();
    #pragma unroll
    for (int mt = 0; mt < 4; mt++) {
        #pragma unroll
        for (int nt = 0; nt < 8; nt++) {
            int ml = wm + mt * 16 + gid;
            int nl = wn + nt * 8 + 2 * tig;
            int n0 = bn + nl;
            float b0 = bias[n0], b1 = bias[n0 + 1];
            __half2 v0 = *(__half2*)&acc[mt][nt][0];
            __half2 v1 = *(__half2*)&acc[mt][nt][1];
            smf[nl * 132 + ml]           = __low2float(v0)  + b0;
            smf[(nl + 1) * 132 + ml]     = __high2float(v0) + b1;
            smf[nl * 132 + ml + 8]       = __low2float(v1)  + b0;
            smf[(nl + 1) * 132 + ml + 8] = __high2float(v1) + b1;
        }
    }
    __syncthreads();
    #pragma unroll
    for (int i = 0; i < 32; i++) {
        int idx = tid + i * 128;
        int row = idx >> 5;
        int m = (idx & 31) << 2;
        size_t gidx = (size_t)(bn + row) * L_DIM + bm + m;
        float4 v = *(float4*)&smf[row * 132 + m];
        float4 r4 = *(const float4*)&R[gidx];
        v.x += r4.x; v.y += r4.y; v.z += r4.z; v.w += r4.w;
        *(float4*)&C[gidx] = v;
    }
}

// ---------------- host launch ----------------
extern "C" void kernel_launch(void* const* d_in, const int* in_sizes, int n_in,
                              void* d_out, int out_size)
{
    const float* x        = (const float*)d_in[0];
    const float* gn_scale = (const float*)d_in[1];
    const float* gn_bias  = (const float*)d_in[2];
    const float* wq = (const float*)d_in[3];
    const float* bq = (const float*)d_in[4];
    const float* wk = (const float*)d_in[5];
    const float* bk = (const float*)d_in[6];
    const float* wv = (const float*)d_in[7];
    const float* bv = (const float*)d_in[8];
    const float* wo = (const float*)d_in[9];
    const float* bo = (const float*)d_in[10];
    float* out = (float*)d_out;

    static f16* p_ht = nullptr;
    if (!p_ht) {
        cudaGetSymbolAddress((void**)&p_ht, g_ht);
        cudaFuncSetAttribute(qkv_kernel,    cudaFuncAttributeMaxDynamicSharedMemorySize, SMEM_BYTES);
        cudaFuncSetAttribute(scores_kernel, cudaFuncAttributeMaxDynamicSharedMemorySize, SC_SMEM);
        cudaFuncSetAttribute(av_kernel,     cudaFuncAttributeMaxDynamicSharedMemorySize, SMEM_BYTES);
        cudaFuncSetAttribute(final_kernel,  cudaFuncAttributeMaxDynamicSharedMemorySize, FSMEM_BYTES);
    }

    const float att_scale = 0.044194173824159216f;   // 512^-0.5

    cvt_w_kernel<<<(C_DIM * C_DIM) / 256, 256>>>(wq, wk, wv, wo);
    gn_kernel<<<N_BATCH * NGROUP, 512>>>(x, gn_scale, gn_bias, p_ht);

    dim3 gq(C_DIM / BN, L_DIM / BM, 3 * N_BATCH);   // (4, 32, 12)
    qkv_kernel<<<gq, 128, SMEM_BYTES>>>(p_ht, att_scale, bq, bk, bv);

    dim3 gs(L_DIM / SBN, L_DIM / SBM, N_BATCH);     // (16, 32, 4)
    scores_kernel<<<gs, 256, SC_SMEM>>>();

    dim3 ga(C_DIM / BN, L_DIM / BM, N_BATCH);       // (4, 32, 4)
    av_kernel<<<ga, 128, SMEM_BYTES>>>();

    final_kernel<<<ga, 128, FSMEM_BYTES>>>(out, bo, x);
}

// round 14
// speedup vs baseline: 1.5979x; 1.5979x over previous
#include <cuda_runtime.h>
#include <cuda_fp16.h>
#include <math.h>
#include <stdint.h>

#define N_BATCH 4
#define C_DIM   512
#define L_DIM   4096
#define NGROUP  32
#define CPG     16
#define GN_EPS  1e-5f
#define CL      ((size_t)C_DIM * L_DIM)
#define LL      ((size_t)L_DIM * L_DIM)

typedef __half f16;

// ---------------- scratch ----------------
__device__ f16   g_ht[N_BATCH * CL];
__device__ f16   g_q [N_BATCH * CL];       // [L, C], pre-scaled by att_scale
__device__ f16   g_k [N_BATCH * CL];       // [L, C]
__device__ f16   g_v [N_BATCH * CL];       // [C, L]
__device__ f16   g_o [N_BATCH * CL];       // [L, C]
__device__ f16   g_p [N_BATCH * LL];       // unnormalized exp(scores)
__device__ float g_psum[N_BATCH * L_DIM * 32];
__device__ f16   g_wq[C_DIM * C_DIM];
__device__ f16   g_wk[C_DIM * C_DIM];
__device__ f16   g_wv[C_DIM * C_DIM];
__device__ f16   g_wo[C_DIM * C_DIM];

__global__ void cvt_w_kernel(const float* __restrict__ wq, const float* __restrict__ wk,
                             const float* __restrict__ wv, const float* __restrict__ wo)
{
    int i = blockIdx.x * 256 + threadIdx.x;
    g_wq[i] = __float2half(wq[i]);
    g_wk[i] = __float2half(wk[i]);
    g_wv[i] = __float2half(wv[i]);
    g_wo[i] = __float2half(wo[i]);
}

// ---------------- GroupNorm -> h_t[L, C] f16 ----------------
__global__ __launch_bounds__(512) void gn_kernel(const float* __restrict__ x,
                                                 const float* __restrict__ scale,
                                                 const float* __restrict__ bias,
                                                 f16* __restrict__ ht)
{
    const int n = blockIdx.x >> 5;
    const int g = blockIdx.x & 31;
    const float* __restrict__ xg = x + ((size_t)n * C_DIM + (size_t)g * CPG) * L_DIM;
    f16* __restrict__ hb = ht + (size_t)n * CL + g * CPG;
    const int tid = threadIdx.x;

    const float4* xv = (const float4*)xg;
    float s = 0.f, ss = 0.f;
    for (int i = tid; i < CPG * L_DIM / 4; i += 512) {
        float4 v = xv[i];
        s  += v.x + v.y + v.z + v.w;
        ss += v.x*v.x + v.y*v.y + v.z*v.z + v.w*v.w;
    }
    __shared__ float rs[512], rss[512];
    rs[tid] = s; rss[tid] = ss;
    __syncthreads();
    for (int st = 256; st > 0; st >>= 1) {
        if (tid < st) { rs[tid] += rs[tid+st]; rss[tid] += rss[tid+st]; }
        __syncthreads();
    }
    const float inv_n = 1.f / (float)(CPG * L_DIM);
    const float mean = rs[0] * inv_n;
    const float var  = rss[0] * inv_n - mean * mean;
    const float rstd = rsqrtf(var + GN_EPS);

    __shared__ float tile[16][260];
    for (int l0 = 0; l0 < L_DIM; l0 += 256) {
        #pragma unroll
        for (int j = 0; j < 2; j++) {
            int vi = tid + j * 512;
            int c  = vi >> 6;
            int lv = vi & 63;
            float4 v = xv[c * (L_DIM/4) + (l0 >> 2) + lv];
            float sc = scale[g*CPG + c] * rstd;
            float bi = bias[g*CPG + c] - mean * sc;
            tile[c][4*lv+0] = v.x*sc + bi;
            tile[c][4*lv+1] = v.y*sc + bi;
            tile[c][4*lv+2] = v.z*sc + bi;
            tile[c][4*lv+3] = v.w*sc + bi;
        }
        __syncthreads();
        #pragma unroll
        for (int j = 0; j < 2; j++) {
            int vi = tid + j * 512;
            int l  = vi >> 2;
            int c4 = vi & 3;
            __half2 p0 = __floats2half2_rn(tile[4*c4+0][l], tile[4*c4+1][l]);
            __half2 p1 = __floats2half2_rn(tile[4*c4+2][l], tile[4*c4+3][l]);
            f16* dst = hb + (size_t)(l0 + l) * C_DIM + 4*c4;
            *(__half2*)(dst)     = p0;
            *(__half2*)(dst + 2) = p1;
        }
        __syncthreads();
    }
}

// ---------------- MMA helpers ----------------
__device__ __forceinline__ void mma_f16(uint32_t* d, const uint32_t* a, const uint32_t* b) {
    asm volatile(
        "mma.sync.aligned.m16n8k16.row.col.f16.f16.f16.f16 "
        "{%0,%1},{%2,%3,%4,%5},{%6,%7},{%0,%1};"
        : "+r"(d[0]), "+r"(d[1])
        : "r"(a[0]), "r"(a[1]), "r"(a[2]), "r"(a[3]), "r"(b[0]), "r"(b[1]));
}

__device__ __forceinline__ void ldsm_x4(uint32_t* r, uint32_t addr) {
    asm volatile("ldmatrix.sync.aligned.m8n8.x4.shared.b16 {%0,%1,%2,%3}, [%4];"
        : "=r"(r[0]), "=r"(r[1]), "=r"(r[2]), "=r"(r[3]) : "r"(addr));
}

#define CP16(dst, src) asm volatile("cp.async.cg.shared.global [%0], [%1], 16;" :: "r"(dst), "l"(src))
#define CP_COMMIT()    asm volatile("cp.async.commit_group;")
#define CP_WAIT(n)     asm volatile("cp.async.wait_group %0;" :: "n"(n))

// 128-thread CTA, 4 warps 2(M)x2(N), warp tile 64x64, CTA tile 128x128, BK=32.
#define BM 128
#define BN 128
#define PITCH 40
#define TILEO (128 * PITCH)
#define STAGEE (2 * TILEO)
#define SMEM_BYTES (2 * STAGEE * 2)     // 40960 B -> 4 CTAs/SM
#define FSMEM_BYTES (128 * 132 * 4)     // 67584 B (final kernel fp32 staging)

#define GEMM_MAINLOOP(A, B, K)                                                      \
    const uint32_t smem_u = (uint32_t)__cvta_generic_to_shared(sm);                 \
    const uint32_t a_off = ((wm + (lane & 15)) * PITCH + ((lane >> 4) << 3)) * 2;   \
    const uint32_t b_off = ((wn + (lane & 7) + ((lane >> 4) << 3)) * PITCH          \
                            + (((lane >> 3) & 1) << 3)) * 2;                        \
    uint32_t acc[4][8][2];                                                          \
    _Pragma("unroll") for (int i = 0; i < 4; i++)                                   \
        _Pragma("unroll") for (int j = 0; j < 8; j++)                               \
            { acc[i][j][0] = 0u; acc[i][j][1] = 0u; }                               \
    auto load_tiles = [&](int k0, int s) {                                          \
        f16* As = sm + s * STAGEE;                                                  \
        f16* Bs = As + TILEO;                                                       \
        _Pragma("unroll") for (int i = 0; i < 4; i++) {                             \
            int id  = tid + i * 128;                                                \
            int row = id >> 2;                                                      \
            int cof = (id & 3) << 3;                                                \
            CP16((uint32_t)__cvta_generic_to_shared(As + row * PITCH + cof),        \
                 (A) + (size_t)(bm + row) * (K) + k0 + cof);                        \
            CP16((uint32_t)__cvta_generic_to_shared(Bs + row * PITCH + cof),        \
                 (B) + (size_t)(bn + row) * (K) + k0 + cof);                        \
        }                                                                           \
    };                                                                              \
    load_tiles(0, 0);                                                               \
    CP_COMMIT();                                                                    \
    int s = 0;                                                                      \
    _Pragma("unroll 1") for (int it = 0; it < (K) / 32; it++) {                     \
        CP_WAIT(0);                                                                 \
        __syncthreads();                                                            \
        if (it + 1 < (K) / 32) { load_tiles((it + 1) << 5, s ^ 1); CP_COMMIT(); }   \
        const uint32_t As_u = smem_u + s * (STAGEE * 2);                            \
        const uint32_t Bs_u = As_u + TILEO * 2;                                     \
        _Pragma("unroll") for (int ks = 0; ks < 2; ks++) {                          \
            const uint32_t kadd = ks * 32;                                          \
            uint32_t a[4][4], b[8][2];                                              \
            _Pragma("unroll") for (int mt = 0; mt < 4; mt++)                        \
                ldsm_x4(a[mt], As_u + a_off + mt * (16 * PITCH * 2) + kadd);        \
            _Pragma("unroll") for (int p = 0; p < 4; p++) {                         \
                uint32_t r[4];                                                      \
                ldsm_x4(r, Bs_u + b_off + p * (16 * PITCH * 2) + kadd);             \
                b[2*p][0]   = r[0]; b[2*p][1]   = r[1];                             \
                b[2*p+1][0] = r[2]; b[2*p+1][1] = r[3];                             \
            }                                                                       \
            _Pragma("unroll") for (int mt = 0; mt < 4; mt++)                        \
                _Pragma("unroll") for (int nt = 0; nt < 8; nt++)                    \
                    mma_f16(acc[mt][nt], a[mt], b[nt]);                             \
        }                                                                           \
        s ^= 1;                                                                     \
    }

// ================= fused QKV projection =================
__global__ __launch_bounds__(128, 4)
void qkv_kernel(const f16* __restrict__ ht, float att_scale,
                const float* __restrict__ bq, const float* __restrict__ bk,
                const float* __restrict__ bv)
{
    extern __shared__ f16 sm[];
    const int which = blockIdx.z >> 2;
    const int nb    = blockIdx.z & 3;
    const f16* A = ht + (size_t)nb * CL;
    const f16* B = (which == 0) ? g_wq : (which == 1) ? g_wk : g_wv;
    const float* bias = (which == 0) ? bq : (which == 1) ? bk : bv;

    const int tid = threadIdx.x;
    const int bm = blockIdx.y * BM;
    const int bn = blockIdx.x * BN;
    const int lane = tid & 31;
    const int warp = tid >> 5;
    const int wm   = (warp >> 1) << 6;
    const int wn   = (warp & 1) << 6;
    const int gid  = lane >> 2;
    const int tig  = lane & 3;

    GEMM_MAINLOOP(A, B, C_DIM)

    if (which <= 1) {
        const float scl = (which == 0) ? att_scale : 1.f;
        f16* C = ((which == 0) ? g_q : g_k) + (size_t)nb * CL;
        #pragma unroll
        for (int mt = 0; mt < 4; mt++) {
            #pragma unroll
            for (int nt = 0; nt < 8; nt++) {
                int m0 = bm + wm + mt * 16 + gid;
                int n0 = bn + wn + nt * 8 + 2 * tig;
                float b0 = bias[n0], b1 = bias[n0 + 1];
                __half2 v0 = *(__half2*)&acc[mt][nt][0];
                __half2 v1 = *(__half2*)&acc[mt][nt][1];
                float d0 = (__low2float(v0)  + b0) * scl;
                float d1 = (__high2float(v0) + b1) * scl;
                float d2 = (__low2float(v1)  + b0) * scl;
                float d3 = (__high2float(v1) + b1) * scl;
                *(__half2*)&C[(size_t)m0 * C_DIM + n0]       = __floats2half2_rn(d0, d1);
                *(__half2*)&C[(size_t)(m0 + 8) * C_DIM + n0] = __floats2half2_rn(d2, d3);
            }
        }
    } else {
        f16* smh = sm;
        __syncthreads();
        #pragma unroll
        for (int mt = 0; mt < 4; mt++) {
            #pragma unroll
            for (int nt = 0; nt < 8; nt++) {
                int ml = wm + mt * 16 + gid;
                int nl = wn + nt * 8 + 2 * tig;
                int n0 = bn + nl;
                float b0 = bias[n0], b1 = bias[n0 + 1];
                __half2 v0 = *(__half2*)&acc[mt][nt][0];
                __half2 v1 = *(__half2*)&acc[mt][nt][1];
                smh[nl * 136 + ml]           = __float2half(__low2float(v0)  + b0);
                smh[(nl + 1) * 136 + ml]     = __float2half(__high2float(v0) + b1);
                smh[nl * 136 + ml + 8]       = __float2half(__low2float(v1)  + b0);
                smh[(nl + 1) * 136 + ml + 8] = __float2half(__high2float(v1) + b1);
            }
        }
        __syncthreads();
        f16* C = g_v + (size_t)nb * CL;
        #pragma unroll
        for (int i = 0; i < 16; i++) {
            int idx = tid + i * 128;
            int row = idx >> 4;
            int m = (idx & 15) << 3;
            uint4 v = *(uint4*)&smh[row * 136 + m];
            *(uint4*)&C[(size_t)(bn + row) * L_DIM + bm + m] = v;
        }
    }
}

// ================= scores: P = exp(q k^T) f16 + partial row sums =================
__global__ __launch_bounds__(128, 4)
void scores_kernel()
{
    extern __shared__ f16 sm[];
    const int nb = blockIdx.z;
    const f16* A = g_q + (size_t)nb * CL;
    const f16* B = g_k + (size_t)nb * CL;
    f16* C = g_p + (size_t)nb * LL;

    const int tid = threadIdx.x;
    const int bm = blockIdx.y * BM;
    const int bn = blockIdx.x * BN;
    const int lane = tid & 31;
    const int warp = tid >> 5;
    const int wm   = (warp >> 1) << 6;
    const int wn   = (warp & 1) << 6;
    const int gid  = lane >> 2;
    const int tig  = lane & 3;

    GEMM_MAINLOOP(A, B, C_DIM)

    // epilogue: exp + f16 store + per-row partial sums (each warp covers 64 cols)
    float* part = (float*)sm;           // [2][128]
    __syncthreads();
    #pragma unroll
    for (int mt = 0; mt < 4; mt++) {
        int m0 = bm + wm + mt * 16 + gid;
        float sA = 0.f, sB = 0.f;
        #pragma unroll
        for (int nt = 0; nt < 8; nt++) {
            int n0 = bn + wn + nt * 8 + 2 * tig;
            __half2 v0 = *(__half2*)&acc[mt][nt][0];
            __half2 v1 = *(__half2*)&acc[mt][nt][1];
            float e0 = __expf(__low2float(v0));
            float e1 = __expf(__high2float(v0));
            float e2 = __expf(__low2float(v1));
            float e3 = __expf(__high2float(v1));
            sA += e0 + e1; sB += e2 + e3;
            *(__half2*)&C[(size_t)m0 * L_DIM + n0]       = __floats2half2_rn(e0, e1);
            *(__half2*)&C[(size_t)(m0 + 8) * L_DIM + n0] = __floats2half2_rn(e2, e3);
        }
        sA += __shfl_xor_sync(0xffffffffu, sA, 1);
        sA += __shfl_xor_sync(0xffffffffu, sA, 2);
        sB += __shfl_xor_sync(0xffffffffu, sB, 1);
        sB += __shfl_xor_sync(0xffffffffu, sB, 2);
        if (tig == 0) {
            part[(warp & 1) * 128 + wm + mt * 16 + gid]     = sA;
            part[(warp & 1) * 128 + wm + mt * 16 + gid + 8] = sB;
        }
    }
    __syncthreads();
    {
        float sv = part[tid] + part[128 + tid];
        g_psum[((size_t)nb * L_DIM + bm + tid) * 32 + blockIdx.x] = sv;
    }
}

// ================= AV: O = (P V^T) / rowsum (psum reduced in-prologue) =================
__global__ __launch_bounds__(128, 4)
void av_kernel()
{
    extern __shared__ f16 sm[];
    __shared__ float sinv[128];
    const int nb = blockIdx.z;
    const f16* A = g_p + (size_t)nb * LL;
    const f16* B = g_v + (size_t)nb * CL;
    f16* C = g_o + (size_t)nb * CL;

    const int tid = threadIdx.x;
    const int bm = blockIdx.y * BM;
    const int bn = blockIdx.x * BN;
    const int lane = tid & 31;
    const int warp = tid >> 5;
    const int wm   = (warp >> 1) << 6;
    const int wn   = (warp & 1) << 6;
    const int gid  = lane >> 2;
    const int tig  = lane & 3;

    {
        const float4* pp = (const float4*)(g_psum + ((size_t)nb * L_DIM + bm + tid) * 32);
        float sv = 0.f;
        #pragma unroll
        for (int i = 0; i < 8; i++) {
            float4 v = pp[i];
            sv += v.x + v.y + v.z + v.w;
        }
        sinv[tid] = 1.f / sv;
    }

    GEMM_MAINLOOP(A, B, L_DIM)

    #pragma unroll
    for (int mt = 0; mt < 4; mt++) {
        int ml = wm + mt * 16 + gid;
        int m0 = bm + ml;
        float i0 = sinv[ml], i1 = sinv[ml + 8];
        #pragma unroll
        for (int nt = 0; nt < 8; nt++) {
            int n0 = bn + wn + nt * 8 + 2 * tig;
            __half2 v0 = *(__half2*)&acc[mt][nt][0];
            __half2 v1 = *(__half2*)&acc[mt][nt][1];
            *(__half2*)&C[(size_t)m0 * C_DIM + n0] =
                __floats2half2_rn(__low2float(v0) * i0, __high2float(v0) * i0);
            *(__half2*)&C[(size_t)(m0 + 8) * C_DIM + n0] =
                __floats2half2_rn(__low2float(v1) * i1, __high2float(v1) * i1);
        }
    }
}

// ================= final projection: out = (O x wo^T)^T + bo + x =================
__global__ __launch_bounds__(128, 3)
void final_kernel(float* __restrict__ Cg, const float* __restrict__ bias,
                  const float* __restrict__ resg)
{
    extern __shared__ f16 sm[];
    const int tid = threadIdx.x;
    const int bm = blockIdx.y * BM;
    const int bn = blockIdx.x * BN;
    const f16* A = g_o + (size_t)blockIdx.z * CL;
    const f16* B = g_wo;
    const float* R = resg + (size_t)blockIdx.z * CL;
    float* C = Cg + (size_t)blockIdx.z * CL;

    const int lane = tid & 31;
    const int warp = tid >> 5;
    const int wm   = (warp >> 1) << 6;
    const int wn   = (warp & 1) << 6;
    const int gid  = lane >> 2;
    const int tig  = lane & 3;

    GEMM_MAINLOOP(A, B, C_DIM)

    // fp32 transposed + bias + residual via smem staging ([n=128][m=128], pitch 132)
    float* smf = (float*)sm;
    __syncthreads();
    #pragma unroll
    for (int mt = 0; mt < 4; mt++) {
        #pragma unroll
        for (int nt = 0; nt < 8; nt++) {
            int ml = wm + mt * 16 + gid;
            int nl = wn + nt * 8 + 2 * tig;
            int n0 = bn + nl;
            float b0 = bias[n0], b1 = bias[n0 + 1];
            __half2 v0 = *(__half2*)&acc[mt][nt][0];
            __half2 v1 = *(__half2*)&acc[mt][nt][1];
            smf[nl * 132 + ml]           = __low2float(v0)  + b0;
            smf[(nl + 1) * 132 + ml]     = __high2float(v0) + b1;
            smf[nl * 132 + ml + 8]       = __low2float(v1)  + b0;
            smf[(nl + 1) * 132 + ml + 8] = __high2float(v1) + b1;
        }
    }
    __syncthreads();
    #pragma unroll
    for (int i = 0; i < 32; i++) {
        int idx = tid + i * 128;
        int row = idx >> 5;
        int m = (idx & 31) << 2;
        size_t gidx = (size_t)(bn + row) * L_DIM + bm + m;
        float4 v = *(float4*)&smf[row * 132 + m];
        float4 r4 = *(const float4*)&R[gidx];
        v.x += r4.x; v.y += r4.y; v.z += r4.z; v.w += r4.w;
        *(float4*)&C[gidx] = v;
    }
}

// ---------------- host launch ----------------
extern "C" void kernel_launch(void* const* d_in, const int* in_sizes, int n_in,
                              void* d_out, int out_size)
{
    const float* x        = (const float*)d_in[0];
    const float* gn_scale = (const float*)d_in[1];
    const float* gn_bias  = (const float*)d_in[2];
    const float* wq = (const float*)d_in[3];
    const float* bq = (const float*)d_in[4];
    const float* wk = (const float*)d_in[5];
    const float* bk = (const float*)d_in[6];
    const float* wv = (const float*)d_in[7];
    const float* bv = (const float*)d_in[8];
    const float* wo = (const float*)d_in[9];
    const float* bo = (const float*)d_in[10];
    float* out = (float*)d_out;

    static f16* p_ht = nullptr;
    if (!p_ht) {
        cudaGetSymbolAddress((void**)&p_ht, g_ht);
        cudaFuncSetAttribute(qkv_kernel,    cudaFuncAttributeMaxDynamicSharedMemorySize, SMEM_BYTES);
        cudaFuncSetAttribute(scores_kernel, cudaFuncAttributeMaxDynamicSharedMemorySize, SMEM_BYTES);
        cudaFuncSetAttribute(av_kernel,     cudaFuncAttributeMaxDynamicSharedMemorySize, SMEM_BYTES);
        cudaFuncSetAttribute(final_kernel,  cudaFuncAttributeMaxDynamicSharedMemorySize, FSMEM_BYTES);
    }

    const float att_scale = 0.044194173824159216f;   // 512^-0.5

    cvt_w_kernel<<<(C_DIM * C_DIM) / 256, 256>>>(wq, wk, wv, wo);
    gn_kernel<<<N_BATCH * NGROUP, 512>>>(x, gn_scale, gn_bias, p_ht);

    dim3 gq(C_DIM / BN, L_DIM / BM, 3 * N_BATCH);   // (4, 32, 12)
    qkv_kernel<<<gq, 128, SMEM_BYTES>>>(p_ht, att_scale, bq, bk, bv);

    dim3 gs(L_DIM / BN, L_DIM / BM, N_BATCH);       // (32, 32, 4)
    scores_kernel<<<gs, 128, SMEM_BYTES>>>();

    dim3 ga(C_DIM / BN, L_DIM / BM, N_BATCH);       // (4, 32, 4)
    av_kernel<<<ga, 128, SMEM_BYTES>>>();

    final_kernel<<<ga, 128, FSMEM_BYTES>>>(out, bo, x);
}

// round 15
// speedup vs baseline: 1.6322x; 1.0215x over previous
#include <cuda_runtime.h>
#include <cuda_fp16.h>
#include <math.h>
#include <stdint.h>

#define N_BATCH 4
#define C_DIM   512
#define L_DIM   4096
#define NGROUP  32
#define CPG     16
#define GN_EPS  1e-5f
#define CL      ((size_t)C_DIM * L_DIM)
#define LL      ((size_t)L_DIM * L_DIM)

typedef __half f16;

// ---------------- scratch ----------------
__device__ f16   g_ht[N_BATCH * CL];
__device__ f16   g_q [N_BATCH * CL];       // [L, C], pre-scaled by att_scale
__device__ f16   g_k [N_BATCH * CL];       // [L, C]
__device__ f16   g_v [N_BATCH * CL];       // [C, L]
__device__ f16   g_o [N_BATCH * CL];       // [L, C]
__device__ f16   g_p [N_BATCH * LL];       // unnormalized exp(scores)
__device__ float g_psum[N_BATCH * L_DIM * 32];
__device__ f16   g_wq[C_DIM * C_DIM];
__device__ f16   g_wk[C_DIM * C_DIM];
__device__ f16   g_wv[C_DIM * C_DIM];
__device__ f16   g_wo[C_DIM * C_DIM];

__global__ void cvt_w_kernel(const float* __restrict__ wq, const float* __restrict__ wk,
                             const float* __restrict__ wv, const float* __restrict__ wo)
{
    int i = blockIdx.x * 256 + threadIdx.x;
    g_wq[i] = __float2half(wq[i]);
    g_wk[i] = __float2half(wk[i]);
    g_wv[i] = __float2half(wv[i]);
    g_wo[i] = __float2half(wo[i]);
}

// ---------------- GroupNorm -> h_t[L, C] f16 ----------------
__global__ __launch_bounds__(512) void gn_kernel(const float* __restrict__ x,
                                                 const float* __restrict__ scale,
                                                 const float* __restrict__ bias,
                                                 f16* __restrict__ ht)
{
    const int n = blockIdx.x >> 5;
    const int g = blockIdx.x & 31;
    const float* __restrict__ xg = x + ((size_t)n * C_DIM + (size_t)g * CPG) * L_DIM;
    f16* __restrict__ hb = ht + (size_t)n * CL + g * CPG;
    const int tid = threadIdx.x;

    const float4* xv = (const float4*)xg;
    float s = 0.f, ss = 0.f;
    for (int i = tid; i < CPG * L_DIM / 4; i += 512) {
        float4 v = xv[i];
        s  += v.x + v.y + v.z + v.w;
        ss += v.x*v.x + v.y*v.y + v.z*v.z + v.w*v.w;
    }
    __shared__ float rs[512], rss[512];
    rs[tid] = s; rss[tid] = ss;
    __syncthreads();
    for (int st = 256; st > 0; st >>= 1) {
        if (tid < st) { rs[tid] += rs[tid+st]; rss[tid] += rss[tid+st]; }
        __syncthreads();
    }
    const float inv_n = 1.f / (float)(CPG * L_DIM);
    const float mean = rs[0] * inv_n;
    const float var  = rss[0] * inv_n - mean * mean;
    const float rstd = rsqrtf(var + GN_EPS);

    __shared__ float tile[16][260];
    for (int l0 = 0; l0 < L_DIM; l0 += 256) {
        #pragma unroll
        for (int j = 0; j < 2; j++) {
            int vi = tid + j * 512;
            int c  = vi >> 6;
            int lv = vi & 63;
            float4 v = xv[c * (L_DIM/4) + (l0 >> 2) + lv];
            float sc = scale[g*CPG + c] * rstd;
            float bi = bias[g*CPG + c] - mean * sc;
            tile[c][4*lv+0] = v.x*sc + bi;
            tile[c][4*lv+1] = v.y*sc + bi;
            tile[c][4*lv+2] = v.z*sc + bi;
            tile[c][4*lv+3] = v.w*sc + bi;
        }
        __syncthreads();
        #pragma unroll
        for (int j = 0; j < 2; j++) {
            int vi = tid + j * 512;
            int l  = vi >> 2;
            int c4 = vi & 3;
            __half2 p0 = __floats2half2_rn(tile[4*c4+0][l], tile[4*c4+1][l]);
            __half2 p1 = __floats2half2_rn(tile[4*c4+2][l], tile[4*c4+3][l]);
            f16* dst = hb + (size_t)(l0 + l) * C_DIM + 4*c4;
            *(__half2*)(dst)     = p0;
            *(__half2*)(dst + 2) = p1;
        }
        __syncthreads();
    }
}

// ---------------- MMA helpers ----------------
__device__ __forceinline__ void mma_f16(uint32_t* d, const uint32_t* a, const uint32_t* b) {
    asm volatile(
        "mma.sync.aligned.m16n8k16.row.col.f16.f16.f16.f16 "
        "{%0,%1},{%2,%3,%4,%5},{%6,%7},{%0,%1};"
        : "+r"(d[0]), "+r"(d[1])
        : "r"(a[0]), "r"(a[1]), "r"(a[2]), "r"(a[3]), "r"(b[0]), "r"(b[1]));
}

__device__ __forceinline__ void ldsm_x4(uint32_t* r, uint32_t addr) {
    asm volatile("ldmatrix.sync.aligned.m8n8.x4.shared.b16 {%0,%1,%2,%3}, [%4];"
        : "=r"(r[0]), "=r"(r[1]), "=r"(r[2]), "=r"(r[3]) : "r"(addr));
}

#define CP16(dst, src) asm volatile("cp.async.cg.shared.global [%0], [%1], 16;" :: "r"(dst), "l"(src))
#define CP_COMMIT()    asm volatile("cp.async.commit_group;")
#define CP_WAIT(n)     asm volatile("cp.async.wait_group %0;" :: "n"(n))

// 128-thread CTA, 4 warps 2(M)x2(N), warp tile 64x64, CTA tile 128x128, BK=32.
#define BM 128
#define BN 128
#define PITCH 40
#define TILEO (128 * PITCH)
#define STAGEE (2 * TILEO)
#define SMEM_BYTES (2 * STAGEE * 2)     // 40960 B -> 4 CTAs/SM
#define FSMEM_BYTES (128 * 132 * 4)     // 67584 B (final kernel fp32 staging)

#define GEMM_MAINLOOP(A, B, K)                                                      \
    const uint32_t smem_u = (uint32_t)__cvta_generic_to_shared(sm);                 \
    const uint32_t a_off = ((wm + (lane & 15)) * PITCH + ((lane >> 4) << 3)) * 2;   \
    const uint32_t b_off = ((wn + (lane & 7) + ((lane >> 4) << 3)) * PITCH          \
                            + (((lane >> 3) & 1) << 3)) * 2;                        \
    uint32_t acc[4][8][2];                                                          \
    _Pragma("unroll") for (int i = 0; i < 4; i++)                                   \
        _Pragma("unroll") for (int j = 0; j < 8; j++)                               \
            { acc[i][j][0] = 0u; acc[i][j][1] = 0u; }                               \
    auto load_tiles = [&](int k0, int s) {                                          \
        f16* As = sm + s * STAGEE;                                                  \
        f16* Bs = As + TILEO;                                                       \
        _Pragma("unroll") for (int i = 0; i < 4; i++) {                             \
            int id  = tid + i * 128;                                                \
            int row = id >> 2;                                                      \
            int cof = (id & 3) << 3;                                                \
            CP16((uint32_t)__cvta_generic_to_shared(As + row * PITCH + cof),        \
                 (A) + (size_t)(bm + row) * (K) + k0 + cof);                        \
            CP16((uint32_t)__cvta_generic_to_shared(Bs + row * PITCH + cof),        \
                 (B) + (size_t)(bn + row) * (K) + k0 + cof);                        \
        }                                                                           \
    };                                                                              \
    load_tiles(0, 0);                                                               \
    CP_COMMIT();                                                                    \
    int s = 0;                                                                      \
    _Pragma("unroll 1") for (int it = 0; it < (K) / 32; it++) {                     \
        CP_WAIT(0);                                                                 \
        __syncthreads();                                                            \
        if (it + 1 < (K) / 32) { load_tiles((it + 1) << 5, s ^ 1); CP_COMMIT(); }   \
        const uint32_t As_u = smem_u + s * (STAGEE * 2);                            \
        const uint32_t Bs_u = As_u + TILEO * 2;                                     \
        _Pragma("unroll") for (int ks = 0; ks < 2; ks++) {                          \
            const uint32_t kadd = ks * 32;                                          \
            uint32_t a[4][4], b[8][2];                                              \
            _Pragma("unroll") for (int mt = 0; mt < 4; mt++)                        \
                ldsm_x4(a[mt], As_u + a_off + mt * (16 * PITCH * 2) + kadd);        \
            _Pragma("unroll") for (int p = 0; p < 4; p++) {                         \
                uint32_t r[4];                                                      \
                ldsm_x4(r, Bs_u + b_off + p * (16 * PITCH * 2) + kadd);             \
                b[2*p][0]   = r[0]; b[2*p][1]   = r[1];                             \
                b[2*p+1][0] = r[2]; b[2*p+1][1] = r[3];                             \
            }                                                                       \
            _Pragma("unroll") for (int mt = 0; mt < 4; mt++)                        \
                _Pragma("unroll") for (int nt = 0; nt < 8; nt++)                    \
                    mma_f16(acc[mt][nt], a[mt], b[nt]);                             \
        }                                                                           \
        s ^= 1;                                                                     \
    }

// ================= fused QKV projection =================
__global__ __launch_bounds__(128, 4)
void qkv_kernel(const f16* __restrict__ ht, float att_scale,
                const float* __restrict__ bq, const float* __restrict__ bk,
                const float* __restrict__ bv)
{
    extern __shared__ f16 sm[];
    const int which = blockIdx.z >> 2;
    const int nb    = blockIdx.z & 3;
    const f16* A = ht + (size_t)nb * CL;
    const f16* B = (which == 0) ? g_wq : (which == 1) ? g_wk : g_wv;
    const float* bias = (which == 0) ? bq : (which == 1) ? bk : bv;

    const int tid = threadIdx.x;
    const int bm = blockIdx.y * BM;
    const int bn = blockIdx.x * BN;
    const int lane = tid & 31;
    const int warp = tid >> 5;
    const int wm   = (warp >> 1) << 6;
    const int wn   = (warp & 1) << 6;
    const int gid  = lane >> 2;
    const int tig  = lane & 3;

    GEMM_MAINLOOP(A, B, C_DIM)

    if (which <= 1) {
        const float scl = (which == 0) ? att_scale : 1.f;
        f16* C = ((which == 0) ? g_q : g_k) + (size_t)nb * CL;
        #pragma unroll
        for (int mt = 0; mt < 4; mt++) {
            #pragma unroll
            for (int nt = 0; nt < 8; nt++) {
                int m0 = bm + wm + mt * 16 + gid;
                int n0 = bn + wn + nt * 8 + 2 * tig;
                float b0 = bias[n0], b1 = bias[n0 + 1];
                __half2 v0 = *(__half2*)&acc[mt][nt][0];
                __half2 v1 = *(__half2*)&acc[mt][nt][1];
                float d0 = (__low2float(v0)  + b0) * scl;
                float d1 = (__high2float(v0) + b1) * scl;
                float d2 = (__low2float(v1)  + b0) * scl;
                float d3 = (__high2float(v1) + b1) * scl;
                *(__half2*)&C[(size_t)m0 * C_DIM + n0]       = __floats2half2_rn(d0, d1);
                *(__half2*)&C[(size_t)(m0 + 8) * C_DIM + n0] = __floats2half2_rn(d2, d3);
            }
        }
    } else {
        f16* smh = sm;
        __syncthreads();
        #pragma unroll
        for (int mt = 0; mt < 4; mt++) {
            #pragma unroll
            for (int nt = 0; nt < 8; nt++) {
                int ml = wm + mt * 16 + gid;
                int nl = wn + nt * 8 + 2 * tig;
                int n0 = bn + nl;
                float b0 = bias[n0], b1 = bias[n0 + 1];
                __half2 v0 = *(__half2*)&acc[mt][nt][0];
                __half2 v1 = *(__half2*)&acc[mt][nt][1];
                smh[nl * 136 + ml]           = __float2half(__low2float(v0)  + b0);
                smh[(nl + 1) * 136 + ml]     = __float2half(__high2float(v0) + b1);
                smh[nl * 136 + ml + 8]       = __float2half(__low2float(v1)  + b0);
                smh[(nl + 1) * 136 + ml + 8] = __float2half(__high2float(v1) + b1);
            }
        }
        __syncthreads();
        f16* C = g_v + (size_t)nb * CL;
        #pragma unroll
        for (int i = 0; i < 16; i++) {
            int idx = tid + i * 128;
            int row = idx >> 4;
            int m = (idx & 15) << 3;
            uint4 v = *(uint4*)&smh[row * 136 + m];
            *(uint4*)&C[(size_t)(bn + row) * L_DIM + bm + m] = v;
        }
    }
}

// ================= scores: P = exp(q k^T) f16, staged coalesced stores =================
__global__ __launch_bounds__(128, 4)
void scores_kernel()
{
    extern __shared__ f16 sm[];
    const int nb = blockIdx.z;
    const f16* A = g_q + (size_t)nb * CL;
    const f16* B = g_k + (size_t)nb * CL;
    f16* C = g_p + (size_t)nb * LL;

    const int tid = threadIdx.x;
    const int bm = blockIdx.y * BM;
    const int bn = blockIdx.x * BN;
    const int lane = tid & 31;
    const int warp = tid >> 5;
    const int wm   = (warp >> 1) << 6;
    const int wn   = (warp & 1) << 6;
    const int gid  = lane >> 2;
    const int tig  = lane & 3;

    GEMM_MAINLOOP(A, B, C_DIM)

    // ---- exp + repack f16 into acc + per-row sums ----
    float rowA[4], rowB[4];
    #pragma unroll
    for (int mt = 0; mt < 4; mt++) { rowA[mt] = 0.f; rowB[mt] = 0.f; }
    #pragma unroll
    for (int mt = 0; mt < 4; mt++) {
        #pragma unroll
        for (int nt = 0; nt < 8; nt++) {
            __half2 v0 = *(__half2*)&acc[mt][nt][0];
            __half2 v1 = *(__half2*)&acc[mt][nt][1];
            float e0 = __expf(__low2float(v0));
            float e1 = __expf(__high2float(v0));
            float e2 = __expf(__low2float(v1));
            float e3 = __expf(__high2float(v1));
            rowA[mt] += e0 + e1;
            rowB[mt] += e2 + e3;
            __half2 h0 = __floats2half2_rn(e0, e1);
            __half2 h1 = __floats2half2_rn(e2, e3);
            acc[mt][nt][0] = *(uint32_t*)&h0;
            acc[mt][nt][1] = *(uint32_t*)&h1;
        }
    }

    // ---- partial row sums -> g_psum ----
    float* part = (float*)sm;           // [2][128]
    __syncthreads();                    // mainloop smem reads done
    #pragma unroll
    for (int mt = 0; mt < 4; mt++) {
        float sA = rowA[mt], sB = rowB[mt];
        sA += __shfl_xor_sync(0xffffffffu, sA, 1);
        sA += __shfl_xor_sync(0xffffffffu, sA, 2);
        sB += __shfl_xor_sync(0xffffffffu, sB, 1);
        sB += __shfl_xor_sync(0xffffffffu, sB, 2);
        if (tig == 0) {
            part[(warp & 1) * 128 + wm + mt * 16 + gid]     = sA;
            part[(warp & 1) * 128 + wm + mt * 16 + gid + 8] = sB;
        }
    }
    __syncthreads();
    {
        float sv = part[tid] + part[128 + tid];
        g_psum[((size_t)nb * L_DIM + bm + tid) * 32 + blockIdx.x] = sv;
    }

    // ---- staged coalesced stores: two passes of 64 rows ----
    f16* smh = sm;                      // [64][136]
    #pragma unroll
    for (int p = 0; p < 2; p++) {
        __syncthreads();
        if ((warp >> 1) == p) {         // warps with wm == p*64 own these rows
            #pragma unroll
            for (int mt = 0; mt < 4; mt++) {
                #pragma unroll
                for (int nt = 0; nt < 8; nt++) {
                    int ml = mt * 16 + gid;              // local row 0..63
                    int nl = wn + nt * 8 + 2 * tig;
                    *(__half2*)&smh[ml * 136 + nl]       = *(__half2*)&acc[mt][nt][0];
                    *(__half2*)&smh[(ml + 8) * 136 + nl] = *(__half2*)&acc[mt][nt][1];
                }
            }
        }
        __syncthreads();
        #pragma unroll
        for (int i = 0; i < 8; i++) {
            int idx = tid + i * 128;
            int row = idx >> 4;                          // 0..63
            int m = (idx & 15) << 3;
            uint4 v = *(uint4*)&smh[row * 136 + m];
            *(uint4*)&C[(size_t)(bm + p * 64 + row) * L_DIM + bn + m] = v;
        }
    }
}

// ================= AV: O = (P V^T) / rowsum (psum reduced in-prologue) =================
__global__ __launch_bounds__(128, 4)
void av_kernel()
{
    extern __shared__ f16 sm[];
    __shared__ float sinv[128];
    const int nb = blockIdx.z;
    const f16* A = g_p + (size_t)nb * LL;
    const f16* B = g_v + (size_t)nb * CL;
    f16* C = g_o + (size_t)nb * CL;

    const int tid = threadIdx.x;
    const int bm = blockIdx.y * BM;
    const int bn = blockIdx.x * BN;
    const int lane = tid & 31;
    const int warp = tid >> 5;
    const int wm   = (warp >> 1) << 6;
    const int wn   = (warp & 1) << 6;
    const int gid  = lane >> 2;
    const int tig  = lane & 3;

    {
        const float4* pp = (const float4*)(g_psum + ((size_t)nb * L_DIM + bm + tid) * 32);
        float sv = 0.f;
        #pragma unroll
        for (int i = 0; i < 8; i++) {
            float4 v = pp[i];
            sv += v.x + v.y + v.z + v.w;
        }
        sinv[tid] = 1.f / sv;
    }

    GEMM_MAINLOOP(A, B, L_DIM)

    #pragma unroll
    for (int mt = 0; mt < 4; mt++) {
        int ml = wm + mt * 16 + gid;
        int m0 = bm + ml;
        float i0 = sinv[ml], i1 = sinv[ml + 8];
        #pragma unroll
        for (int nt = 0; nt < 8; nt++) {
            int n0 = bn + wn + nt * 8 + 2 * tig;
            __half2 v0 = *(__half2*)&acc[mt][nt][0];
            __half2 v1 = *(__half2*)&acc[mt][nt][1];
            *(__half2*)&C[(size_t)m0 * C_DIM + n0] =
                __floats2half2_rn(__low2float(v0) * i0, __high2float(v0) * i0);
            *(__half2*)&C[(size_t)(m0 + 8) * C_DIM + n0] =
                __floats2half2_rn(__low2float(v1) * i1, __high2float(v1) * i1);
        }
    }
}

// ================= final projection: out = (O x wo^T)^T + bo + x =================
__global__ __launch_bounds__(128, 3)
void final_kernel(float* __restrict__ Cg, const float* __restrict__ bias,
                  const float* __restrict__ resg)
{
    extern __shared__ f16 sm[];
    const int tid = threadIdx.x;
    const int bm = blockIdx.y * BM;
    const int bn = blockIdx.x * BN;
    const f16* A = g_o + (size_t)blockIdx.z * CL;
    const f16* B = g_wo;
    const float* R = resg + (size_t)blockIdx.z * CL;
    float* C = Cg + (size_t)blockIdx.z * CL;

    const int lane = tid & 31;
    const int warp = tid >> 5;
    const int wm   = (warp >> 1) << 6;
    const int wn   = (warp & 1) << 6;
    const int gid  = lane >> 2;
    const int tig  = lane & 3;

    GEMM_MAINLOOP(A, B, C_DIM)

    float* smf = (float*)sm;
    __syncthreads();
    #pragma unroll
    for (int mt = 0; mt < 4; mt++) {
        #pragma unroll
        for (int nt = 0; nt < 8; nt++) {
            int ml = wm + mt * 16 + gid;
            int nl = wn + nt * 8 + 2 * tig;
            int n0 = bn + nl;
            float b0 = bias[n0], b1 = bias[n0 + 1];
            __half2 v0 = *(__half2*)&acc[mt][nt][0];
            __half2 v1 = *(__half2*)&acc[mt][nt][1];
            smf[nl * 132 + ml]           = __low2float(v0)  + b0;
            smf[(nl + 1) * 132 + ml]     = __high2float(v0) + b1;
            smf[nl * 132 + ml + 8]       = __low2float(v1)  + b0;
            smf[(nl + 1) * 132 + ml + 8] = __high2float(v1) + b1;
        }
    }
    __syncthreads();
    #pragma unroll
    for (int i = 0; i < 32; i++) {
        int idx = tid + i * 128;
        int row = idx >> 5;
        int m = (idx & 31) << 2;
        size_t gidx = (size_t)(bn + row) * L_DIM + bm + m;
        float4 v = *(float4*)&smf[row * 132 + m];
        float4 r4 = *(const float4*)&R[gidx];
        v.x += r4.x; v.y += r4.y; v.z += r4.z; v.w += r4.w;
        *(float4*)&C[gidx] = v;
    }
}

// ---------------- host launch ----------------
extern "C" void kernel_launch(void* const* d_in, const int* in_sizes, int n_in,
                              void* d_out, int out_size)
{
    const float* x        = (const float*)d_in[0];
    const float* gn_scale = (const float*)d_in[1];
    const float* gn_bias  = (const float*)d_in[2];
    const float* wq = (const float*)d_in[3];
    const float* bq = (const float*)d_in[4];
    const float* wk = (const float*)d_in[5];
    const float* bk = (const float*)d_in[6];
    const float* wv = (const float*)d_in[7];
    const float* bv = (const float*)d_in[8];
    const float* wo = (const float*)d_in[9];
    const float* bo = (const float*)d_in[10];
    float* out = (float*)d_out;

    static f16* p_ht = nullptr;
    if (!p_ht) {
        cudaGetSymbolAddress((void**)&p_ht, g_ht);
        cudaFuncSetAttribute(qkv_kernel,    cudaFuncAttributeMaxDynamicSharedMemorySize, SMEM_BYTES);
        cudaFuncSetAttribute(scores_kernel, cudaFuncAttributeMaxDynamicSharedMemorySize, SMEM_BYTES);
        cudaFuncSetAttribute(av_kernel,     cudaFuncAttributeMaxDynamicSharedMemorySize, SMEM_BYTES);
        cudaFuncSetAttribute(final_kernel,  cudaFuncAttributeMaxDynamicSharedMemorySize, FSMEM_BYTES);
    }

    const float att_scale = 0.044194173824159216f;   // 512^-0.5

    cvt_w_kernel<<<(C_DIM * C_DIM) / 256, 256>>>(wq, wk, wv, wo);
    gn_kernel<<<N_BATCH * NGROUP, 512>>>(x, gn_scale, gn_bias, p_ht);

    dim3 gq(C_DIM / BN, L_DIM / BM, 3 * N_BATCH);   // (4, 32, 12)
    qkv_kernel<<<gq, 128, SMEM_BYTES>>>(p_ht, att_scale, bq, bk, bv);

    dim3 gs(L_DIM / BN, L_DIM / BM, N_BATCH);       // (32, 32, 4)
    scores_kernel<<<gs, 128, SMEM_BYTES>>>();

    dim3 ga(C_DIM / BN, L_DIM / BM, N_BATCH);       // (4, 32, 4)
    av_kernel<<<ga, 128, SMEM_BYTES>>>();

    final_kernel<<<ga, 128, FSMEM_BYTES>>>(out, bo, x);
}